// round 11
// baseline (speedup 1.0000x reference)
#include <cuda_runtime.h>
#include <cuda_fp16.h>
#include <math.h>
#include <stdint.h>

#define NN 100000
#define NE 1600000
#define INCH 512
#define HID 128
#define NCLS 40

// ---------------- device scratch ----------------
__device__ unsigned g_t1h[(size_t)NN * 64];   // x@W1 (UNSCALED) as fp16x2
__device__ unsigned g_hh [(size_t)NN * 64];   // relu(agg1) as fp16x2
__device__ unsigned g_t2h[(size_t)NN * 20];   // (h@W2)*dinv as fp16x2
__device__ __half   g_w1h[INCH * HID];        // W1 transposed [n][k] fp16
__device__ __half   g_w2h[HID * NCLS];        // W2 transposed [n][k] fp16
__device__ float    g_dinv[NN];
__device__ int      g_indeg[NN];
__device__ int      g_rowstart[NN + 1];
__device__ int      g_cursor[NN];
__device__ int2     g_csre[NE];               // (src, dinv[src] bits)
__device__ int      g_part[256];
__device__ int      g_is64;

// ---------------- helpers ----------------
__device__ __forceinline__ void mma_f16(float* d, const uint32_t* a,
                                        const uint32_t* b, const float* c) {
    asm volatile(
        "mma.sync.aligned.m16n8k16.row.col.f32.f16.f16.f32 "
        "{%0,%1,%2,%3}, {%4,%5,%6,%7}, {%8,%9}, {%10,%11,%12,%13};\n"
        : "=f"(d[0]), "=f"(d[1]), "=f"(d[2]), "=f"(d[3])
        : "r"(a[0]), "r"(a[1]), "r"(a[2]), "r"(a[3]),
          "r"(b[0]), "r"(b[1]),
          "f"(c[0]), "f"(c[1]), "f"(c[2]), "f"(c[3]));
}

__device__ __forceinline__ void cpa16(void* smem, const void* gmem, int sz) {
    unsigned s = (unsigned)__cvta_generic_to_shared(smem);
    asm volatile("cp.async.cg.shared.global [%0], [%1], 16, %2;\n"
                 :: "r"(s), "l"(gmem), "r"(sz));
}

__device__ __forceinline__ unsigned pack_h2(float a, float b) {
    __half2 v = __floats2half2_rn(a, b);
    return *(unsigned*)&v;
}

__device__ __forceinline__ float2 unpack_h2(unsigned u) {
    return __half22float2(*(__half2*)&u);
}

// ---------------- init: zero + dtype detect + weight convert ----------------
__global__ void k_init(const int* ei, const float* __restrict__ W1,
                       const float* __restrict__ W2) {
    int i = blockIdx.x * blockDim.x + threadIdx.x;
    if (i < NN) { g_indeg[i] = 0; g_cursor[i] = 0; }
    if (i < INCH * HID) {               // W1[k][n] -> g_w1h[n][k]
        int k = i >> 7, n = i & 127;
        g_w1h[n * INCH + k] = __float2half(W1[i]);
    }
    if (i < HID * NCLS) {               // W2[k][n] -> g_w2h[n][k]
        int k = i / NCLS, n = i % NCLS;
        g_w2h[n * HID + k] = __float2half(W2[i]);
    }
    if (i == 0) {
        int is64 = 1;
        for (int j = 0; j < 64; j++)
            if (ei[2 * j + 1] != 0) { is64 = 0; break; }
        g_is64 = is64;
    }
}

__device__ __forceinline__ int ld_idx(const void* ei, long long pos, int is64) {
    if (is64) return (int)((const long long*)ei)[pos];
    return ((const int*)ei)[pos];
}

// ---------------- degree ----------------
__global__ void k_deg(const void* ei) {
    int e = blockIdx.x * blockDim.x + threadIdx.x;
    if (e < NE) {
        int is64 = g_is64;
        int d = ld_idx(ei, (long long)NE + e, is64);
        atomicAdd(&g_indeg[d], 1);
    }
}

// ---------------- scan (2-phase; base computed per block) ----------------
__global__ void k_scan1() {
    __shared__ int s[1024];
    int i = blockIdx.x * 1024 + threadIdx.x;
    int v = (i < NN) ? g_indeg[i] : 0;
    s[threadIdx.x] = v; __syncthreads();
    for (int off = 512; off > 0; off >>= 1) {
        if (threadIdx.x < off) s[threadIdx.x] += s[threadIdx.x + off];
        __syncthreads();
    }
    if (threadIdx.x == 0) g_part[blockIdx.x] = s[0];
}

__global__ void k_scan3() {
    __shared__ int s[1024];
    __shared__ int pb[128];
    int bid = blockIdx.x;
    if (threadIdx.x < 128)
        pb[threadIdx.x] = (threadIdx.x < bid && threadIdx.x < 98) ? g_part[threadIdx.x] : 0;
    int i = bid * 1024 + threadIdx.x;
    int v = (i < NN) ? g_indeg[i] : 0;
    s[threadIdx.x] = v;
    __syncthreads();
    for (int off = 64; off > 0; off >>= 1) {
        if (threadIdx.x < off) pb[threadIdx.x] += pb[threadIdx.x + off];
        __syncthreads();
    }
    int base = pb[0];
    int val = v;
    for (int off = 1; off < 1024; off <<= 1) {
        int t = 0;
        if (threadIdx.x >= off) t = s[threadIdx.x - off];
        __syncthreads();
        val += t; s[threadIdx.x] = val;
        __syncthreads();
    }
    if (i < NN) {
        g_rowstart[i] = base + val - v;
        g_dinv[i] = rsqrtf((float)(v + 1));
        if (i == NN - 1) g_rowstart[NN] = base + val;
    }
}

// ---------------- CSR fill: (src, dinv[src]) per edge ----------------
__global__ void k_csr(const void* ei) {
    int e = blockIdx.x * blockDim.x + threadIdx.x;
    if (e < NE) {
        int is64 = g_is64;
        int s = ld_idx(ei, e, is64);
        int d = ld_idx(ei, (long long)NE + e, is64);
        int pos = g_rowstart[d] + atomicAdd(&g_cursor[d], 1);
        g_csre[pos] = make_int2(s, __float_as_int(g_dinv[s]));
    }
}

// ---------------- GEMM1 (fp16 mma, 4-stage cp.async, 3 CTAs/SM) ----------------
// block 128M x 128N, 8 warps (4x2), warp tile 32x64, K stage 16, 4-deep pipeline
#define G1_STAGES 4
#define G1_ABYTES (G1_STAGES * 128 * 24 * 4)
#define G1_SMEM   (G1_ABYTES + G1_STAGES * 128 * 24 * 2)

__global__ void __launch_bounds__(256, 3) k_gemm1(const float* __restrict__ A) {
    extern __shared__ __align__(16) char dsm[];
    float*  As = (float*)dsm;                      // [4][128][24]
    __half* Bs = (__half*)(dsm + G1_ABYTES);       // [4][128][24]
#define AS(b, r, c) As[(((b) * 128) + (r)) * 24 + (c)]
#define BS(b, r, c) Bs[(((b) * 128) + (r)) * 24 + (c)]

    int t = threadIdx.x, lane = t & 31, w = t >> 5;
    int wm = w >> 1, wn = w & 1;
    int row0 = blockIdx.x * 128;
    int g = lane >> 2, tig = lane & 3;
    int rm = wm * 32, cn = wn * 64;

    int arow = t >> 1;
    int acol = (t & 1) * 8;
    int bn   = t >> 1;
    int bc   = (t & 1) * 8;

    float acc[2][8][4];
#pragma unroll
    for (int i = 0; i < 2; i++)
#pragma unroll
        for (int j = 0; j < 8; j++)
#pragma unroll
            for (int q = 0; q < 4; q++) acc[i][j][q] = 0.f;

    int aok = (row0 + arow < NN) ? 16 : 0;
    const float* abase = &A[(size_t)(row0 + arow) * INCH];

#define LOAD_STAGE(buf, k0)                                               \
    {                                                                     \
        const float* ap = abase + (k0) + acol;                            \
        cpa16(&AS(buf, arow, acol), ap, aok);                             \
        cpa16(&AS(buf, arow, acol + 4), ap + 4, aok);                     \
        cpa16(&BS(buf, bn, bc), &g_w1h[bn * INCH + (k0) + bc], 16);       \
    }

    LOAD_STAGE(0, 0);
    asm volatile("cp.async.commit_group;\n");
    LOAD_STAGE(1, 16);
    asm volatile("cp.async.commit_group;\n");
    LOAD_STAGE(2, 32);
    asm volatile("cp.async.commit_group;\n");

    for (int s = 0; s < 32; s++) {
        int buf = s & 3;
        asm volatile("cp.async.wait_group 2;\n");
        __syncthreads();

        uint32_t af[2][4];
#pragma unroll
        for (int i = 0; i < 2; i++) {
            int r = rm + i * 16 + g;
            float2 v0 = *(const float2*)&AS(buf, r,     tig * 2);
            float2 v1 = *(const float2*)&AS(buf, r + 8, tig * 2);
            float2 v2 = *(const float2*)&AS(buf, r,     tig * 2 + 8);
            float2 v3 = *(const float2*)&AS(buf, r + 8, tig * 2 + 8);
            af[i][0] = pack_h2(v0.x, v0.y);
            af[i][1] = pack_h2(v1.x, v1.y);
            af[i][2] = pack_h2(v2.x, v2.y);
            af[i][3] = pack_h2(v3.x, v3.y);
        }
#pragma unroll
        for (int j = 0; j < 8; j++) {
            int col = cn + j * 8 + g;
            uint32_t bf[2];
            bf[0] = *(const uint32_t*)&BS(buf, col, tig * 2);
            bf[1] = *(const uint32_t*)&BS(buf, col, tig * 2 + 8);
            mma_f16(acc[0][j], af[0], bf, acc[0][j]);
            mma_f16(acc[1][j], af[1], bf, acc[1][j]);
        }
        if (s < 29) LOAD_STAGE((s + 3) & 3, (s + 3) * 16);
        asm volatile("cp.async.commit_group;\n");
    }
#undef LOAD_STAGE
#undef AS
#undef BS

#pragma unroll
    for (int i = 0; i < 2; i++) {
        int r0 = row0 + rm + i*16 + g;
        int r1 = r0 + 8;
#pragma unroll
        for (int j = 0; j < 8; j++) {
            int cp = (cn >> 1) + j*4 + tig;
            if (r0 < NN)
                g_t1h[(size_t)r0 * 64 + cp] = pack_h2(acc[i][j][0], acc[i][j][1]);
            if (r1 < NN)
                g_t1h[(size_t)r1 * 64 + cp] = pack_h2(acc[i][j][2], acc[i][j][3]);
        }
    }
}

// ---------------- AGG1: warp/node, 8-unroll, per-edge dinv from csre ----------------
__global__ void __launch_bounds__(256) k_agg1(const float* __restrict__ b1) {
    int warp = (blockIdx.x * blockDim.x + threadIdx.x) >> 5;
    if (warp >= NN) return;
    int lane = threadIdx.x & 31;
    int node = warp;
    float dn = g_dinv[node];
    const uint2* __restrict__ T = (const uint2*)g_t1h;   // 32 uint2 per row
    const int2* __restrict__ E = g_csre;
    uint2 sv = T[(size_t)node * 32 + lane];
    float2 p0 = unpack_h2(sv.x), p1 = unpack_h2(sv.y);
    float ax = p0.x * dn, ay = p0.y * dn, az = p1.x * dn, aw = p1.y * dn;
    int e0 = g_rowstart[node], e1 = g_rowstart[node + 1];
    int e = e0;
#define EDGE(q, v)                                                     \
    {                                                                  \
        float dd = __int_as_float((q).y);                              \
        float2 a = unpack_h2((v).x), c = unpack_h2((v).y);             \
        ax += a.x * dd; ay += a.y * dd;                                \
        az += c.x * dd; aw += c.y * dd;                                \
    }
    for (; e + 8 <= e1; e += 8) {
        int2 q0 = E[e],   q1 = E[e+1], q2 = E[e+2], q3 = E[e+3];
        int2 q4 = E[e+4], q5 = E[e+5], q6 = E[e+6], q7 = E[e+7];
        uint2 v0 = T[(size_t)q0.x * 32 + lane];
        uint2 v1 = T[(size_t)q1.x * 32 + lane];
        uint2 v2 = T[(size_t)q2.x * 32 + lane];
        uint2 v3 = T[(size_t)q3.x * 32 + lane];
        uint2 v4 = T[(size_t)q4.x * 32 + lane];
        uint2 v5 = T[(size_t)q5.x * 32 + lane];
        uint2 v6 = T[(size_t)q6.x * 32 + lane];
        uint2 v7 = T[(size_t)q7.x * 32 + lane];
        EDGE(q0, v0) EDGE(q1, v1) EDGE(q2, v2) EDGE(q3, v3)
        EDGE(q4, v4) EDGE(q5, v5) EDGE(q6, v6) EDGE(q7, v7)
    }
    for (; e < e1; e++) {
        int2 q = E[e];
        uint2 v = T[(size_t)q.x * 32 + lane];
        EDGE(q, v)
    }
#undef EDGE
    float4 bb = *(const float4*)&b1[lane * 4];
    float hx = fmaxf(ax * dn + bb.x, 0.f);
    float hy = fmaxf(ay * dn + bb.y, 0.f);
    float hz = fmaxf(az * dn + bb.z, 0.f);
    float hw = fmaxf(aw * dn + bb.w, 0.f);
    uint2 o = make_uint2(pack_h2(hx, hy), pack_h2(hz, hw));
    ((uint2*)g_hh)[(size_t)node * 32 + lane] = o;
}

// ---------------- GEMM2 (fp16 mma, 3-buffer pipeline): t2h = fp16((h@W2)*dinv) ----------------
__global__ void __launch_bounds__(128) k_gemm2() {
    __shared__ __align__(16) __half As2[3][128][40];
    __shared__ __align__(16) __half ws2[40][136];
    int t = threadIdx.x, lane = t & 31, w = t >> 5;
    int row0 = blockIdx.x * 128;
    int g = lane >> 2, tig = lane & 3;
    int rm = w * 32;

    for (int i = t; i < NCLS * HID; i += 128)
        ws2[i >> 7][i & 127] = g_w2h[i];

    float acc[2][5][4];
#pragma unroll
    for (int i = 0; i < 2; i++)
#pragma unroll
        for (int j = 0; j < 5; j++)
#pragma unroll
            for (int q = 0; q < 4; q++) acc[i][j][q] = 0.f;

    const __half* hbase = (const __half*)g_hh;

#define LD_STAGE2(buf, st)                                             \
    {                                                                  \
        _Pragma("unroll")                                              \
        for (int i = 0; i < 4; i++) {                                  \
            int f = t + i * 128;                                       \
            int r = f >> 2, c = (f & 3) * 8;                           \
            int ok = (row0 + r < NN) ? 16 : 0;                         \
            cpa16(&As2[buf][r][c],                                     \
                  hbase + (size_t)(row0 + r) * HID + (st) * 32 + c, ok); \
        }                                                              \
        asm volatile("cp.async.commit_group;\n");                      \
    }

    LD_STAGE2(0, 0);
    LD_STAGE2(1, 1);

    for (int st = 0; st < 4; st++) {
        int buf = st % 3;
        asm volatile("cp.async.wait_group 1;\n");
        __syncthreads();
        if (st + 2 < 4) { LD_STAGE2((st + 2) % 3, st + 2); }
        else { asm volatile("cp.async.commit_group;\n"); }

#pragma unroll
        for (int kh = 0; kh < 2; kh++) {
            int k0 = kh * 16;
            uint32_t af[2][4];
#pragma unroll
            for (int i = 0; i < 2; i++) {
                int r = rm + i * 16 + g;
                af[i][0] = *(const uint32_t*)&As2[buf][r    ][k0 + tig * 2];
                af[i][1] = *(const uint32_t*)&As2[buf][r + 8][k0 + tig * 2];
                af[i][2] = *(const uint32_t*)&As2[buf][r    ][k0 + tig * 2 + 8];
                af[i][3] = *(const uint32_t*)&As2[buf][r + 8][k0 + tig * 2 + 8];
            }
#pragma unroll
            for (int j = 0; j < 5; j++) {
                int col = j * 8 + g;
                uint32_t bf[2];
                bf[0] = *(const uint32_t*)&ws2[col][st * 32 + k0 + tig * 2];
                bf[1] = *(const uint32_t*)&ws2[col][st * 32 + k0 + tig * 2 + 8];
                mma_f16(acc[0][j], af[0], bf, acc[0][j]);
                mma_f16(acc[1][j], af[1], bf, acc[1][j]);
            }
        }
    }
#undef LD_STAGE2

#pragma unroll
    for (int i = 0; i < 2; i++) {
        int r0 = row0 + rm + i*16 + g;
        int r1 = r0 + 8;
        float d0 = (r0 < NN) ? g_dinv[r0] : 0.f;
        float d1 = (r1 < NN) ? g_dinv[r1] : 0.f;
#pragma unroll
        for (int j = 0; j < 5; j++) {
            int cp = j*4 + tig;
            if (r0 < NN)
                g_t2h[(size_t)r0 * 20 + cp] = pack_h2(acc[i][j][0]*d0, acc[i][j][1]*d0);
            if (r1 < NN)
                g_t2h[(size_t)r1 * 20 + cp] = pack_h2(acc[i][j][2]*d1, acc[i][j][3]*d1);
        }
    }
}

// ---------------- AGG2 + bias + log_softmax: warp/node, 8-unroll ----------------
__global__ void __launch_bounds__(256) k_agg2(const float* __restrict__ b2,
                                              float* __restrict__ out) {
    int warp = (blockIdx.x * blockDim.x + threadIdx.x) >> 5;
    if (warp >= NN) return;
    int lane = threadIdx.x & 31;
    int node = warp;
    bool act = lane < 20;
    float dn = g_dinv[node];
    int cl = act ? lane : 0;
    float accx = 0.f, accy = 0.f;
    {
        float2 p = unpack_h2(g_t2h[(size_t)node * 20 + cl]);
        if (act) { accx = p.x; accy = p.y; }
    }
    const int2* __restrict__ E = g_csre;
    int e0 = g_rowstart[node], e1 = g_rowstart[node + 1];
    int e = e0;
#define EDGE2(q)                                                       \
    {                                                                  \
        float2 v = unpack_h2(g_t2h[(size_t)(q).x * 20 + cl]);          \
        if (act) { accx += v.x; accy += v.y; }                         \
    }
    for (; e + 8 <= e1; e += 8) {
        int2 q0 = E[e],   q1 = E[e+1], q2 = E[e+2], q3 = E[e+3];
        int2 q4 = E[e+4], q5 = E[e+5], q6 = E[e+6], q7 = E[e+7];
        EDGE2(q0) EDGE2(q1) EDGE2(q2) EDGE2(q3)
        EDGE2(q4) EDGE2(q5) EDGE2(q6) EDGE2(q7)
    }
    for (; e < e1; e++) { int2 q = E[e]; EDGE2(q) }
#undef EDGE2
    float lx = -1e30f, ly = -1e30f;
    if (act) {
        float2 bb = *(const float2*)&b2[lane * 2];
        lx = accx * dn + bb.x;
        ly = accy * dn + bb.y;
    }
    float m = fmaxf(lx, ly);
    for (int off = 16; off > 0; off >>= 1)
        m = fmaxf(m, __shfl_xor_sync(0xFFFFFFFF, m, off));
    float s = act ? (expf(lx - m) + expf(ly - m)) : 0.f;
    for (int off = 16; off > 0; off >>= 1)
        s += __shfl_xor_sync(0xFFFFFFFF, s, off);
    float lse = logf(s) + m;
    if (act) {
        float2 o = make_float2(lx - lse, ly - lse);
        *(float2*)&out[(size_t)node * NCLS + lane * 2] = o;
    }
}

// ---------------- launcher (gemm1 is the 4th launch -> gets profiled) ----------------
extern "C" void kernel_launch(void* const* d_in, const int* in_sizes, int n_in,
                              void* d_out, int out_size) {
    const float* x  = (const float*)d_in[0];
    const void*  ei = d_in[1];
    const float* W1 = (const float*)d_in[2];
    const float* b1 = (const float*)d_in[3];
    const float* W2 = (const float*)d_in[4];
    const float* b2 = (const float*)d_in[5];
    float* out = (float*)d_out;

    cudaFuncSetAttribute(k_gemm1, cudaFuncAttributeMaxDynamicSharedMemorySize,
                         G1_SMEM);

    k_init<<<(NN + 255) / 256, 256>>>((const int*)ei, W1, W2);
    k_deg<<<(NE + 255) / 256, 256>>>(ei);
    k_scan1<<<98, 1024>>>();
    k_gemm1<<<(NN + 127) / 128, 256, G1_SMEM>>>(x);   // 4th launch: profiled
    k_scan3<<<98, 1024>>>();
    k_csr<<<(NE + 255) / 256, 256>>>(ei);
    k_agg1<<<(NN * 32 + 255) / 256, 256>>>(b1);
    k_gemm2<<<(NN + 127) / 128, 128>>>();
    k_agg2<<<(NN * 32 + 255) / 256, 256>>>(b2, out);
}

// round 12
// speedup vs baseline: 1.0888x; 1.0888x over previous
#include <cuda_runtime.h>
#include <cuda_fp16.h>
#include <math.h>
#include <stdint.h>

#define NN 100000
#define NE 1600000
#define INCH 512
#define HID 128
#define NCLS 40

// ---------------- device scratch ----------------
__device__ unsigned g_t1h[(size_t)NN * 64];   // x@W1 (UNSCALED) as fp16x2
__device__ unsigned g_hh [(size_t)NN * 64];   // relu(agg1) as fp16x2
__device__ unsigned g_t2h[(size_t)NN * 20];   // (h@W2)*dinv as fp16x2
__device__ __half   g_w1h[INCH * HID];        // W1 transposed [n][k] fp16
__device__ __half   g_w2h[HID * NCLS];        // W2 transposed [n][k] fp16
__device__ float    g_dinv[NN];
__device__ int      g_indeg[NN];
__device__ int      g_rowstart[NN + 1];
__device__ int      g_cursor[NN];
__device__ int2     g_csre[NE];               // (src, dinv[src] bits)
__device__ int      g_part[256];
__device__ int      g_is64;

// ---------------- helpers ----------------
__device__ __forceinline__ void mma_f16(float* d, const uint32_t* a,
                                        const uint32_t* b, const float* c) {
    asm volatile(
        "mma.sync.aligned.m16n8k16.row.col.f32.f16.f16.f32 "
        "{%0,%1,%2,%3}, {%4,%5,%6,%7}, {%8,%9}, {%10,%11,%12,%13};\n"
        : "=f"(d[0]), "=f"(d[1]), "=f"(d[2]), "=f"(d[3])
        : "r"(a[0]), "r"(a[1]), "r"(a[2]), "r"(a[3]),
          "r"(b[0]), "r"(b[1]),
          "f"(c[0]), "f"(c[1]), "f"(c[2]), "f"(c[3]));
}

__device__ __forceinline__ void cpa16(void* smem, const void* gmem, int sz) {
    unsigned s = (unsigned)__cvta_generic_to_shared(smem);
    asm volatile("cp.async.cg.shared.global [%0], [%1], 16, %2;\n"
                 :: "r"(s), "l"(gmem), "r"(sz));
}

__device__ __forceinline__ unsigned pack_h2(float a, float b) {
    __half2 v = __floats2half2_rn(a, b);
    return *(unsigned*)&v;
}

__device__ __forceinline__ float2 unpack_h2(unsigned u) {
    return __half22float2(*(__half2*)&u);
}

// ---------------- init: zero + dtype detect + weight convert ----------------
__global__ void k_init(const int* ei, const float* __restrict__ W1,
                       const float* __restrict__ W2) {
    int i = blockIdx.x * blockDim.x + threadIdx.x;
    if (i < NN) { g_indeg[i] = 0; g_cursor[i] = 0; }
    if (i < INCH * HID) {               // W1[k][n] -> g_w1h[n][k]
        int k = i >> 7, n = i & 127;
        g_w1h[n * INCH + k] = __float2half(W1[i]);
    }
    if (i < HID * NCLS) {               // W2[k][n] -> g_w2h[n][k]
        int k = i / NCLS, n = i % NCLS;
        g_w2h[n * HID + k] = __float2half(W2[i]);
    }
    if (i == 0) {
        int is64 = 1;
        for (int j = 0; j < 64; j++)
            if (ei[2 * j + 1] != 0) { is64 = 0; break; }
        g_is64 = is64;
    }
}

__device__ __forceinline__ int ld_idx(const void* ei, long long pos, int is64) {
    if (is64) return (int)((const long long*)ei)[pos];
    return ((const int*)ei)[pos];
}

// ---------------- degree ----------------
__global__ void k_deg(const void* ei) {
    int e = blockIdx.x * blockDim.x + threadIdx.x;
    if (e < NE) {
        int is64 = g_is64;
        int d = ld_idx(ei, (long long)NE + e, is64);
        atomicAdd(&g_indeg[d], 1);
    }
}

// ---------------- scan (2-phase; base computed per block) ----------------
__global__ void k_scan1() {
    __shared__ int s[1024];
    int i = blockIdx.x * 1024 + threadIdx.x;
    int v = (i < NN) ? g_indeg[i] : 0;
    s[threadIdx.x] = v; __syncthreads();
    for (int off = 512; off > 0; off >>= 1) {
        if (threadIdx.x < off) s[threadIdx.x] += s[threadIdx.x + off];
        __syncthreads();
    }
    if (threadIdx.x == 0) g_part[blockIdx.x] = s[0];
}

__global__ void k_scan3() {
    __shared__ int s[1024];
    __shared__ int pb[128];
    int bid = blockIdx.x;
    if (threadIdx.x < 128)
        pb[threadIdx.x] = (threadIdx.x < bid && threadIdx.x < 98) ? g_part[threadIdx.x] : 0;
    int i = bid * 1024 + threadIdx.x;
    int v = (i < NN) ? g_indeg[i] : 0;
    s[threadIdx.x] = v;
    __syncthreads();
    for (int off = 64; off > 0; off >>= 1) {
        if (threadIdx.x < off) pb[threadIdx.x] += pb[threadIdx.x + off];
        __syncthreads();
    }
    int base = pb[0];
    int val = v;
    for (int off = 1; off < 1024; off <<= 1) {
        int t = 0;
        if (threadIdx.x >= off) t = s[threadIdx.x - off];
        __syncthreads();
        val += t; s[threadIdx.x] = val;
        __syncthreads();
    }
    if (i < NN) {
        g_rowstart[i] = base + val - v;
        g_dinv[i] = rsqrtf((float)(v + 1));
        if (i == NN - 1) g_rowstart[NN] = base + val;
    }
}

// ---------------- CSR fill: (src, dinv[src]) per edge ----------------
__global__ void k_csr(const void* ei) {
    int e = blockIdx.x * blockDim.x + threadIdx.x;
    if (e < NE) {
        int is64 = g_is64;
        int s = ld_idx(ei, e, is64);
        int d = ld_idx(ei, (long long)NE + e, is64);
        int pos = g_rowstart[d] + atomicAdd(&g_cursor[d], 1);
        g_csre[pos] = make_int2(s, __float_as_int(g_dinv[s]));
    }
}

// ---------------- GEMM1 (fp16 mma, K-stage 32, 3-stage cp.async) ----------------
// block 128M x 128N, 8 warps (4x2), warp tile 32x64, full-cache-line A loads
#define G1_STAGES 3
#define G1_KS     32
#define G1_APITCH 40   // floats (conflict-free: g*8+tig*2 distinct mod 32)
#define G1_BPITCH 40   // halves (conflict-free: g*20+tig distinct mod 32)
#define G1_ABYTES (G1_STAGES * 128 * G1_APITCH * 4)
#define G1_SMEM   (G1_ABYTES + G1_STAGES * 128 * G1_BPITCH * 2)

__global__ void __launch_bounds__(256) k_gemm1(const float* __restrict__ A) {
    extern __shared__ __align__(16) char dsm[];
    float*  As = (float*)dsm;                      // [3][128][40]
    __half* Bs = (__half*)(dsm + G1_ABYTES);       // [3][128][40]
#define AS(b, r, c) As[(((b) * 128) + (r)) * G1_APITCH + (c)]
#define BS(b, r, c) Bs[(((b) * 128) + (r)) * G1_BPITCH + (c)]

    int t = threadIdx.x, lane = t & 31, w = t >> 5;
    int wm = w >> 1, wn = w & 1;
    int row0 = blockIdx.x * 128;
    int g = lane >> 2, tig = lane & 3;
    int rm = wm * 32, cn = wn * 64;

    int arow = t >> 1;           // 0..127
    int acol = (t & 1) * 16;     // 0 or 16 (floats; 64 B per thread, 128 B per row pair)
    int bn   = t >> 1;           // 0..127
    int bc   = (t & 1) * 16;     // 0 or 16 (halves; 32 B per thread)

    float acc[2][8][4];
#pragma unroll
    for (int i = 0; i < 2; i++)
#pragma unroll
        for (int j = 0; j < 8; j++)
#pragma unroll
            for (int q = 0; q < 4; q++) acc[i][j][q] = 0.f;

    int aok = (row0 + arow < NN) ? 16 : 0;
    const float* abase = &A[(size_t)(row0 + arow) * INCH];

#define LOAD_STAGE(buf, k0)                                               \
    {                                                                     \
        const float* ap = abase + (k0) + acol;                            \
        cpa16(&AS(buf, arow, acol),      ap,      aok);                   \
        cpa16(&AS(buf, arow, acol + 4),  ap + 4,  aok);                   \
        cpa16(&AS(buf, arow, acol + 8),  ap + 8,  aok);                   \
        cpa16(&AS(buf, arow, acol + 12), ap + 12, aok);                   \
        cpa16(&BS(buf, bn, bc),     &g_w1h[bn * INCH + (k0) + bc],     16); \
        cpa16(&BS(buf, bn, bc + 8), &g_w1h[bn * INCH + (k0) + bc + 8], 16); \
    }

    LOAD_STAGE(0, 0);
    asm volatile("cp.async.commit_group;\n");
    LOAD_STAGE(1, G1_KS);
    asm volatile("cp.async.commit_group;\n");

    for (int s = 0; s < 16; s++) {
        int buf = s % 3;
        asm volatile("cp.async.wait_group 1;\n");
        __syncthreads();

#pragma unroll
        for (int kh = 0; kh < 2; kh++) {
            int k0 = kh * 16;
            uint32_t af[2][4];
#pragma unroll
            for (int i = 0; i < 2; i++) {
                int r = rm + i * 16 + g;
                float2 v0 = *(const float2*)&AS(buf, r,     k0 + tig * 2);
                float2 v1 = *(const float2*)&AS(buf, r + 8, k0 + tig * 2);
                float2 v2 = *(const float2*)&AS(buf, r,     k0 + tig * 2 + 8);
                float2 v3 = *(const float2*)&AS(buf, r + 8, k0 + tig * 2 + 8);
                af[i][0] = pack_h2(v0.x, v0.y);
                af[i][1] = pack_h2(v1.x, v1.y);
                af[i][2] = pack_h2(v2.x, v2.y);
                af[i][3] = pack_h2(v3.x, v3.y);
            }
#pragma unroll
            for (int j = 0; j < 8; j++) {
                int col = cn + j * 8 + g;
                uint32_t bf[2];
                bf[0] = *(const uint32_t*)&BS(buf, col, k0 + tig * 2);
                bf[1] = *(const uint32_t*)&BS(buf, col, k0 + tig * 2 + 8);
                mma_f16(acc[0][j], af[0], bf, acc[0][j]);
                mma_f16(acc[1][j], af[1], bf, acc[1][j]);
            }
        }
        if (s < 14) LOAD_STAGE((s + 2) % 3, (s + 2) * G1_KS);
        asm volatile("cp.async.commit_group;\n");
    }
#undef LOAD_STAGE
#undef AS
#undef BS

#pragma unroll
    for (int i = 0; i < 2; i++) {
        int r0 = row0 + rm + i*16 + g;
        int r1 = r0 + 8;
#pragma unroll
        for (int j = 0; j < 8; j++) {
            int cp = (cn >> 1) + j*4 + tig;
            if (r0 < NN)
                g_t1h[(size_t)r0 * 64 + cp] = pack_h2(acc[i][j][0], acc[i][j][1]);
            if (r1 < NN)
                g_t1h[(size_t)r1 * 64 + cp] = pack_h2(acc[i][j][2], acc[i][j][3]);
        }
    }
}

// ---------------- AGG1: warp/node, 8-unroll, per-edge dinv from csre ----------------
__global__ void __launch_bounds__(256) k_agg1(const float* __restrict__ b1) {
    int warp = (blockIdx.x * blockDim.x + threadIdx.x) >> 5;
    if (warp >= NN) return;
    int lane = threadIdx.x & 31;
    int node = warp;
    float dn = g_dinv[node];
    const uint2* __restrict__ T = (const uint2*)g_t1h;   // 32 uint2 per row
    const int2* __restrict__ E = g_csre;
    uint2 sv = T[(size_t)node * 32 + lane];
    float2 p0 = unpack_h2(sv.x), p1 = unpack_h2(sv.y);
    float ax = p0.x * dn, ay = p0.y * dn, az = p1.x * dn, aw = p1.y * dn;
    int e0 = g_rowstart[node], e1 = g_rowstart[node + 1];
    int e = e0;
#define EDGE(q, v)                                                     \
    {                                                                  \
        float dd = __int_as_float((q).y);                              \
        float2 a = unpack_h2((v).x), c = unpack_h2((v).y);             \
        ax += a.x * dd; ay += a.y * dd;                                \
        az += c.x * dd; aw += c.y * dd;                                \
    }
    for (; e + 8 <= e1; e += 8) {
        int2 q0 = E[e],   q1 = E[e+1], q2 = E[e+2], q3 = E[e+3];
        int2 q4 = E[e+4], q5 = E[e+5], q6 = E[e+6], q7 = E[e+7];
        uint2 v0 = T[(size_t)q0.x * 32 + lane];
        uint2 v1 = T[(size_t)q1.x * 32 + lane];
        uint2 v2 = T[(size_t)q2.x * 32 + lane];
        uint2 v3 = T[(size_t)q3.x * 32 + lane];
        uint2 v4 = T[(size_t)q4.x * 32 + lane];
        uint2 v5 = T[(size_t)q5.x * 32 + lane];
        uint2 v6 = T[(size_t)q6.x * 32 + lane];
        uint2 v7 = T[(size_t)q7.x * 32 + lane];
        EDGE(q0, v0) EDGE(q1, v1) EDGE(q2, v2) EDGE(q3, v3)
        EDGE(q4, v4) EDGE(q5, v5) EDGE(q6, v6) EDGE(q7, v7)
    }
    for (; e < e1; e++) {
        int2 q = E[e];
        uint2 v = T[(size_t)q.x * 32 + lane];
        EDGE(q, v)
    }
#undef EDGE
    float4 bb = *(const float4*)&b1[lane * 4];
    float hx = fmaxf(ax * dn + bb.x, 0.f);
    float hy = fmaxf(ay * dn + bb.y, 0.f);
    float hz = fmaxf(az * dn + bb.z, 0.f);
    float hw = fmaxf(aw * dn + bb.w, 0.f);
    uint2 o = make_uint2(pack_h2(hx, hy), pack_h2(hz, hw));
    ((uint2*)g_hh)[(size_t)node * 32 + lane] = o;
}

// ---------------- GEMM2 (fp16 mma, 3-buffer pipeline): t2h = fp16((h@W2)*dinv) ----------------
__global__ void __launch_bounds__(128) k_gemm2() {
    __shared__ __align__(16) __half As2[3][128][40];
    __shared__ __align__(16) __half ws2[40][136];
    int t = threadIdx.x, lane = t & 31, w = t >> 5;
    int row0 = blockIdx.x * 128;
    int g = lane >> 2, tig = lane & 3;
    int rm = w * 32;

    for (int i = t; i < NCLS * HID; i += 128)
        ws2[i >> 7][i & 127] = g_w2h[i];

    float acc[2][5][4];
#pragma unroll
    for (int i = 0; i < 2; i++)
#pragma unroll
        for (int j = 0; j < 5; j++)
#pragma unroll
            for (int q = 0; q < 4; q++) acc[i][j][q] = 0.f;

    const __half* hbase = (const __half*)g_hh;

#define LD_STAGE2(buf, st)                                             \
    {                                                                  \
        _Pragma("unroll")                                              \
        for (int i = 0; i < 4; i++) {                                  \
            int f = t + i * 128;                                       \
            int r = f >> 2, c = (f & 3) * 8;                           \
            int ok = (row0 + r < NN) ? 16 : 0;                         \
            cpa16(&As2[buf][r][c],                                     \
                  hbase + (size_t)(row0 + r) * HID + (st) * 32 + c, ok); \
        }                                                              \
        asm volatile("cp.async.commit_group;\n");                      \
    }

    LD_STAGE2(0, 0);
    LD_STAGE2(1, 1);

    for (int st = 0; st < 4; st++) {
        int buf = st % 3;
        asm volatile("cp.async.wait_group 1;\n");
        __syncthreads();
        if (st + 2 < 4) { LD_STAGE2((st + 2) % 3, st + 2); }
        else { asm volatile("cp.async.commit_group;\n"); }

#pragma unroll
        for (int kh = 0; kh < 2; kh++) {
            int k0 = kh * 16;
            uint32_t af[2][4];
#pragma unroll
            for (int i = 0; i < 2; i++) {
                int r = rm + i * 16 + g;
                af[i][0] = *(const uint32_t*)&As2[buf][r    ][k0 + tig * 2];
                af[i][1] = *(const uint32_t*)&As2[buf][r + 8][k0 + tig * 2];
                af[i][2] = *(const uint32_t*)&As2[buf][r    ][k0 + tig * 2 + 8];
                af[i][3] = *(const uint32_t*)&As2[buf][r + 8][k0 + tig * 2 + 8];
            }
#pragma unroll
            for (int j = 0; j < 5; j++) {
                int col = j * 8 + g;
                uint32_t bf[2];
                bf[0] = *(const uint32_t*)&ws2[col][st * 32 + k0 + tig * 2];
                bf[1] = *(const uint32_t*)&ws2[col][st * 32 + k0 + tig * 2 + 8];
                mma_f16(acc[0][j], af[0], bf, acc[0][j]);
                mma_f16(acc[1][j], af[1], bf, acc[1][j]);
            }
        }
    }
#undef LD_STAGE2

#pragma unroll
    for (int i = 0; i < 2; i++) {
        int r0 = row0 + rm + i*16 + g;
        int r1 = r0 + 8;
        float d0 = (r0 < NN) ? g_dinv[r0] : 0.f;
        float d1 = (r1 < NN) ? g_dinv[r1] : 0.f;
#pragma unroll
        for (int j = 0; j < 5; j++) {
            int cp = j*4 + tig;
            if (r0 < NN)
                g_t2h[(size_t)r0 * 20 + cp] = pack_h2(acc[i][j][0]*d0, acc[i][j][1]*d0);
            if (r1 < NN)
                g_t2h[(size_t)r1 * 20 + cp] = pack_h2(acc[i][j][2]*d1, acc[i][j][3]*d1);
        }
    }
}

// ---------------- AGG2 + bias + log_softmax: warp/node, 8-unroll ----------------
__global__ void __launch_bounds__(256) k_agg2(const float* __restrict__ b2,
                                              float* __restrict__ out) {
    int warp = (blockIdx.x * blockDim.x + threadIdx.x) >> 5;
    if (warp >= NN) return;
    int lane = threadIdx.x & 31;
    int node = warp;
    bool act = lane < 20;
    float dn = g_dinv[node];
    int cl = act ? lane : 0;
    float accx = 0.f, accy = 0.f;
    {
        float2 p = unpack_h2(g_t2h[(size_t)node * 20 + cl]);
        if (act) { accx = p.x; accy = p.y; }
    }
    const int2* __restrict__ E = g_csre;
    int e0 = g_rowstart[node], e1 = g_rowstart[node + 1];
    int e = e0;
#define EDGE2(q)                                                       \
    {                                                                  \
        float2 v = unpack_h2(g_t2h[(size_t)(q).x * 20 + cl]);          \
        if (act) { accx += v.x; accy += v.y; }                         \
    }
    for (; e + 8 <= e1; e += 8) {
        int2 q0 = E[e],   q1 = E[e+1], q2 = E[e+2], q3 = E[e+3];
        int2 q4 = E[e+4], q5 = E[e+5], q6 = E[e+6], q7 = E[e+7];
        EDGE2(q0) EDGE2(q1) EDGE2(q2) EDGE2(q3)
        EDGE2(q4) EDGE2(q5) EDGE2(q6) EDGE2(q7)
    }
    for (; e < e1; e++) { int2 q = E[e]; EDGE2(q) }
#undef EDGE2
    float lx = -1e30f, ly = -1e30f;
    if (act) {
        float2 bb = *(const float2*)&b2[lane * 2];
        lx = accx * dn + bb.x;
        ly = accy * dn + bb.y;
    }
    float m = fmaxf(lx, ly);
    for (int off = 16; off > 0; off >>= 1)
        m = fmaxf(m, __shfl_xor_sync(0xFFFFFFFF, m, off));
    float s = act ? (expf(lx - m) + expf(ly - m)) : 0.f;
    for (int off = 16; off > 0; off >>= 1)
        s += __shfl_xor_sync(0xFFFFFFFF, s, off);
    float lse = logf(s) + m;
    if (act) {
        float2 o = make_float2(lx - lse, ly - lse);
        *(float2*)&out[(size_t)node * NCLS + lane * 2] = o;
    }
}

// ---------------- launcher (gemm1 is the 4th launch -> gets profiled) ----------------
extern "C" void kernel_launch(void* const* d_in, const int* in_sizes, int n_in,
                              void* d_out, int out_size) {
    const float* x  = (const float*)d_in[0];
    const void*  ei = d_in[1];
    const float* W1 = (const float*)d_in[2];
    const float* b1 = (const float*)d_in[3];
    const float* W2 = (const float*)d_in[4];
    const float* b2 = (const float*)d_in[5];
    float* out = (float*)d_out;

    cudaFuncSetAttribute(k_gemm1, cudaFuncAttributeMaxDynamicSharedMemorySize,
                         G1_SMEM);

    k_init<<<(NN + 255) / 256, 256>>>((const int*)ei, W1, W2);
    k_deg<<<(NE + 255) / 256, 256>>>(ei);
    k_scan1<<<98, 1024>>>();
    k_gemm1<<<(NN + 127) / 128, 256, G1_SMEM>>>(x);   // 4th launch: profiled
    k_scan3<<<98, 1024>>>();
    k_csr<<<(NE + 255) / 256, 256>>>(ei);
    k_agg1<<<(NN * 32 + 255) / 256, 256>>>(b1);
    k_gemm2<<<(NN + 127) / 128, 128>>>();
    k_agg2<<<(NN * 32 + 255) / 256, 256>>>(b2, out);
}

// round 14
// speedup vs baseline: 1.0908x; 1.0018x over previous
#include <cuda_runtime.h>
#include <cuda_fp16.h>
#include <math.h>
#include <stdint.h>

#define NN 100000
#define NE 1600000
#define INCH 512
#define HID 128
#define NCLS 40

// ---------------- device scratch ----------------
__device__ unsigned g_t1h[(size_t)NN * 64];   // x@W1 (UNSCALED) as fp16x2
__device__ unsigned g_hh [(size_t)NN * 64];   // relu(agg1) as fp16x2
__device__ unsigned g_t2h[(size_t)NN * 20];   // (h@W2)*dinv as fp16x2
__device__ __half   g_w1h[INCH * HID];        // W1 transposed [n][k] fp16
__device__ __half   g_w2h[HID * NCLS];        // W2 transposed [n][k] fp16
__device__ float    g_dinv[NN];
__device__ int      g_indeg[NN];
__device__ int      g_rowstart[NN + 1];
__device__ int      g_cursor[NN];
__device__ int2     g_csre[NE];               // (src, dinv[src] bits)
__device__ int      g_part[256];
__device__ int      g_is64;

// ---------------- helpers ----------------
__device__ __forceinline__ void mma_f16(float* d, const uint32_t* a,
                                        const uint32_t* b, const float* c) {
    asm volatile(
        "mma.sync.aligned.m16n8k16.row.col.f32.f16.f16.f32 "
        "{%0,%1,%2,%3}, {%4,%5,%6,%7}, {%8,%9}, {%10,%11,%12,%13};\n"
        : "=f"(d[0]), "=f"(d[1]), "=f"(d[2]), "=f"(d[3])
        : "r"(a[0]), "r"(a[1]), "r"(a[2]), "r"(a[3]),
          "r"(b[0]), "r"(b[1]),
          "f"(c[0]), "f"(c[1]), "f"(c[2]), "f"(c[3]));
}

__device__ __forceinline__ void cpa16(void* smem, const void* gmem, int sz) {
    unsigned s = (unsigned)__cvta_generic_to_shared(smem);
    asm volatile("cp.async.cg.shared.global [%0], [%1], 16, %2;\n"
                 :: "r"(s), "l"(gmem), "r"(sz));
}

__device__ __forceinline__ unsigned pack_h2(float a, float b) {
    __half2 v = __floats2half2_rn(a, b);
    return *(unsigned*)&v;
}

__device__ __forceinline__ float2 unpack_h2(unsigned u) {
    return __half22float2(*(__half2*)&u);
}

// ---------------- init: zero + dtype detect + weight convert ----------------
__global__ void k_init(const int* ei, const float* __restrict__ W1,
                       const float* __restrict__ W2) {
    int i = blockIdx.x * blockDim.x + threadIdx.x;
    if (i < NN) { g_indeg[i] = 0; g_cursor[i] = 0; }
    if (i < INCH * HID) {               // W1[k][n] -> g_w1h[n][k]
        int k = i >> 7, n = i & 127;
        g_w1h[n * INCH + k] = __float2half(W1[i]);
    }
    if (i < HID * NCLS) {               // W2[k][n] -> g_w2h[n][k]
        int k = i / NCLS, n = i % NCLS;
        g_w2h[n * HID + k] = __float2half(W2[i]);
    }
    if (i == 0) {
        int is64 = 1;
        for (int j = 0; j < 64; j++)
            if (ei[2 * j + 1] != 0) { is64 = 0; break; }
        g_is64 = is64;
    }
}

__device__ __forceinline__ int ld_idx(const void* ei, long long pos, int is64) {
    if (is64) return (int)((const long long*)ei)[pos];
    return ((const int*)ei)[pos];
}

// ---------------- degree ----------------
__global__ void k_deg(const void* ei) {
    int e = blockIdx.x * blockDim.x + threadIdx.x;
    if (e < NE) {
        int is64 = g_is64;
        int d = ld_idx(ei, (long long)NE + e, is64);
        atomicAdd(&g_indeg[d], 1);
    }
}

// ---------------- scan (2-phase; base computed per block) ----------------
__global__ void k_scan1() {
    __shared__ int s[1024];
    int i = blockIdx.x * 1024 + threadIdx.x;
    int v = (i < NN) ? g_indeg[i] : 0;
    s[threadIdx.x] = v; __syncthreads();
    for (int off = 512; off > 0; off >>= 1) {
        if (threadIdx.x < off) s[threadIdx.x] += s[threadIdx.x + off];
        __syncthreads();
    }
    if (threadIdx.x == 0) g_part[blockIdx.x] = s[0];
}

__global__ void k_scan3() {
    __shared__ int s[1024];
    __shared__ int pb[128];
    int bid = blockIdx.x;
    if (threadIdx.x < 128)
        pb[threadIdx.x] = (threadIdx.x < bid && threadIdx.x < 98) ? g_part[threadIdx.x] : 0;
    int i = bid * 1024 + threadIdx.x;
    int v = (i < NN) ? g_indeg[i] : 0;
    s[threadIdx.x] = v;
    __syncthreads();
    for (int off = 64; off > 0; off >>= 1) {
        if (threadIdx.x < off) pb[threadIdx.x] += pb[threadIdx.x + off];
        __syncthreads();
    }
    int base = pb[0];
    int val = v;
    for (int off = 1; off < 1024; off <<= 1) {
        int t = 0;
        if (threadIdx.x >= off) t = s[threadIdx.x - off];
        __syncthreads();
        val += t; s[threadIdx.x] = val;
        __syncthreads();
    }
    if (i < NN) {
        g_rowstart[i] = base + val - v;
        g_dinv[i] = rsqrtf((float)(v + 1));
        if (i == NN - 1) g_rowstart[NN] = base + val;
    }
}

// ---------------- CSR fill: (src, dinv[src]) per edge ----------------
__global__ void k_csr(const void* ei) {
    int e = blockIdx.x * blockDim.x + threadIdx.x;
    if (e < NE) {
        int is64 = g_is64;
        int s = ld_idx(ei, e, is64);
        int d = ld_idx(ei, (long long)NE + e, is64);
        int pos = g_rowstart[d] + atomicAdd(&g_cursor[d], 1);
        g_csre[pos] = make_int2(s, __float_as_int(g_dinv[s]));
    }
}

// ---------------- GEMM1 (fp16 mma, fp16 A-smem, 3-buf single-sync) ----------------
// block 128M x 128N, 8 warps (4x2), warp tile 32x64, K stage 16
// A: producer LDG fp32 -> cvt fp16 -> STS (reg-prefetch 1 stage ahead); B: cp.async
__global__ void __launch_bounds__(256) k_gemm1(const float* __restrict__ A) {
    __shared__ __align__(16) __half As[3][128][24];   // fp16, pitch 24 halves
    __shared__ __align__(16) __half Bs[3][128][24];   // fp16 W1 n-major
    int t = threadIdx.x, lane = t & 31, w = t >> 5;
    int wm = w >> 1, wn = w & 1;
    int row0 = blockIdx.x * 128;
    int g = lane >> 2, tig = lane & 3;
    int rm = wm * 32, cn = wn * 64;

    int arow = t >> 1;           // 0..127
    int ac8  = (t & 1) * 8;      // half/float offset 0 or 8
    int bn   = t >> 1;
    int bc   = (t & 1) * 8;

    float acc[2][8][4];
#pragma unroll
    for (int i = 0; i < 2; i++)
#pragma unroll
        for (int j = 0; j < 8; j++)
#pragma unroll
            for (int q = 0; q < 4; q++) acc[i][j][q] = 0.f;

    bool aok = (row0 + arow) < NN;
    const float* abase = &A[(size_t)(row0 + arow) * INCH + ac8];

    float4 rA0, rA1;
#define LDG_A(k0)                                                       \
    {                                                                   \
        const float4* ap = (const float4*)(abase + (k0));               \
        rA0 = aok ? ap[0] : make_float4(0.f, 0.f, 0.f, 0.f);            \
        rA1 = aok ? ap[1] : make_float4(0.f, 0.f, 0.f, 0.f);            \
    }
#define STS_A(buf)                                                      \
    {                                                                   \
        uint4 v;                                                        \
        v.x = pack_h2(rA0.x, rA0.y); v.y = pack_h2(rA0.z, rA0.w);       \
        v.z = pack_h2(rA1.x, rA1.y); v.w = pack_h2(rA1.z, rA1.w);       \
        *(uint4*)&As[buf][arow][ac8] = v;                               \
    }
#define CPA_B(buf, k0)                                                  \
    cpa16(&Bs[buf][bn][bc], &g_w1h[bn * INCH + (k0) + bc], 16);

    // prologue: stages 0,1 into bufs 0,1; prefetch stage 2 into regs
    LDG_A(0);  STS_A(0); CPA_B(0, 0);
    asm volatile("cp.async.commit_group;\n");
    LDG_A(16); STS_A(1); CPA_B(1, 16);
    asm volatile("cp.async.commit_group;\n");
    LDG_A(32);

    for (int s = 0; s < 32; s++) {
        int cur = s % 3;
        asm volatile("cp.async.wait_group 1;\n");
        __syncthreads();
        if (s + 2 < 32) {
            int nxt = (s + 2) % 3;
            STS_A(nxt);
            CPA_B(nxt, (s + 2) * 16);
        }
        asm volatile("cp.async.commit_group;\n");
        if (s + 3 < 32) LDG_A((s + 3) * 16);

        uint32_t af[2][4];
#pragma unroll
        for (int i = 0; i < 2; i++) {
            int r = rm + i * 16 + g;
            af[i][0] = *(const uint32_t*)&As[cur][r    ][tig * 2];
            af[i][1] = *(const uint32_t*)&As[cur][r + 8][tig * 2];
            af[i][2] = *(const uint32_t*)&As[cur][r    ][tig * 2 + 8];
            af[i][3] = *(const uint32_t*)&As[cur][r + 8][tig * 2 + 8];
        }
#pragma unroll
        for (int j = 0; j < 8; j++) {
            int col = cn + j * 8 + g;
            uint32_t bf[2];
            bf[0] = *(const uint32_t*)&Bs[cur][col][tig * 2];
            bf[1] = *(const uint32_t*)&Bs[cur][col][tig * 2 + 8];
            mma_f16(acc[0][j], af[0], bf, acc[0][j]);
            mma_f16(acc[1][j], af[1], bf, acc[1][j]);
        }
    }
#undef LDG_A
#undef STS_A
#undef CPA_B

#pragma unroll
    for (int i = 0; i < 2; i++) {
        int r0 = row0 + rm + i*16 + g;
        int r1 = r0 + 8;
#pragma unroll
        for (int j = 0; j < 8; j++) {
            int cp = (cn >> 1) + j*4 + tig;
            if (r0 < NN)
                g_t1h[(size_t)r0 * 64 + cp] = pack_h2(acc[i][j][0], acc[i][j][1]);
            if (r1 < NN)
                g_t1h[(size_t)r1 * 64 + cp] = pack_h2(acc[i][j][2], acc[i][j][3]);
        }
    }
}

// ---------------- AGG1: warp/node, 8-unroll, per-edge dinv from csre ----------------
__global__ void __launch_bounds__(256) k_agg1(const float* __restrict__ b1) {
    int warp = (blockIdx.x * blockDim.x + threadIdx.x) >> 5;
    if (warp >= NN) return;
    int lane = threadIdx.x & 31;
    int node = warp;
    float dn = g_dinv[node];
    const uint2* __restrict__ T = (const uint2*)g_t1h;
    const int2* __restrict__ E = g_csre;
    uint2 sv = T[(size_t)node * 32 + lane];
    float2 p0 = unpack_h2(sv.x), p1 = unpack_h2(sv.y);
    float ax = p0.x * dn, ay = p0.y * dn, az = p1.x * dn, aw = p1.y * dn;
    int e0 = g_rowstart[node], e1 = g_rowstart[node + 1];
    int e = e0;
#define EDGE(q, v)                                                     \
    {                                                                  \
        float dd = __int_as_float((q).y);                              \
        float2 a = unpack_h2((v).x), c = unpack_h2((v).y);             \
        ax += a.x * dd; ay += a.y * dd;                                \
        az += c.x * dd; aw += c.y * dd;                                \
    }
    for (; e + 8 <= e1; e += 8) {
        int2 q0 = E[e],   q1 = E[e+1], q2 = E[e+2], q3 = E[e+3];
        int2 q4 = E[e+4], q5 = E[e+5], q6 = E[e+6], q7 = E[e+7];
        uint2 v0 = T[(size_t)q0.x * 32 + lane];
        uint2 v1 = T[(size_t)q1.x * 32 + lane];
        uint2 v2 = T[(size_t)q2.x * 32 + lane];
        uint2 v3 = T[(size_t)q3.x * 32 + lane];
        uint2 v4 = T[(size_t)q4.x * 32 + lane];
        uint2 v5 = T[(size_t)q5.x * 32 + lane];
        uint2 v6 = T[(size_t)q6.x * 32 + lane];
        uint2 v7 = T[(size_t)q7.x * 32 + lane];
        EDGE(q0, v0) EDGE(q1, v1) EDGE(q2, v2) EDGE(q3, v3)
        EDGE(q4, v4) EDGE(q5, v5) EDGE(q6, v6) EDGE(q7, v7)
    }
    for (; e < e1; e++) {
        int2 q = E[e];
        uint2 v = T[(size_t)q.x * 32 + lane];
        EDGE(q, v)
    }
#undef EDGE
    float4 bb = *(const float4*)&b1[lane * 4];
    float hx = fmaxf(ax * dn + bb.x, 0.f);
    float hy = fmaxf(ay * dn + bb.y, 0.f);
    float hz = fmaxf(az * dn + bb.z, 0.f);
    float hw = fmaxf(aw * dn + bb.w, 0.f);
    uint2 o = make_uint2(pack_h2(hx, hy), pack_h2(hz, hw));
    ((uint2*)g_hh)[(size_t)node * 32 + lane] = o;
}

// ---------------- GEMM2 (fp16 mma, 3-buffer pipeline): t2h = fp16((h@W2)*dinv) ----------
__global__ void __launch_bounds__(128) k_gemm2() {
    __shared__ __align__(16) __half As2[3][128][40];
    __shared__ __align__(16) __half ws2[40][136];
    int t = threadIdx.x, lane = t & 31, w = t >> 5;
    int row0 = blockIdx.x * 128;
    int g = lane >> 2, tig = lane & 3;
    int rm = w * 32;

    for (int i = t; i < NCLS * HID; i += 128)
        ws2[i >> 7][i & 127] = g_w2h[i];

    float acc[2][5][4];
#pragma unroll
    for (int i = 0; i < 2; i++)
#pragma unroll
        for (int j = 0; j < 5; j++)
#pragma unroll
            for (int q = 0; q < 4; q++) acc[i][j][q] = 0.f;

    const __half* hbase = (const __half*)g_hh;

#define LD_STAGE2(buf, st)                                             \
    {                                                                  \
        _Pragma("unroll")                                              \
        for (int i = 0; i < 4; i++) {                                  \
            int f = t + i * 128;                                       \
            int r = f >> 2, c = (f & 3) * 8;                           \
            int ok = (row0 + r < NN) ? 16 : 0;                         \
            cpa16(&As2[buf][r][c],                                     \
                  hbase + (size_t)(row0 + r) * HID + (st) * 32 + c, ok); \
        }                                                              \
        asm volatile("cp.async.commit_group;\n");                      \
    }

    LD_STAGE2(0, 0);
    LD_STAGE2(1, 1);

    for (int st = 0; st < 4; st++) {
        int buf = st % 3;
        asm volatile("cp.async.wait_group 1;\n");
        __syncthreads();
        if (st + 2 < 4) { LD_STAGE2((st + 2) % 3, st + 2); }
        else { asm volatile("cp.async.commit_group;\n"); }

#pragma unroll
        for (int kh = 0; kh < 2; kh++) {
            int k0 = kh * 16;
            uint32_t af[2][4];
#pragma unroll
            for (int i = 0; i < 2; i++) {
                int r = rm + i * 16 + g;
                af[i][0] = *(const uint32_t*)&As2[buf][r    ][k0 + tig * 2];
                af[i][1] = *(const uint32_t*)&As2[buf][r + 8][k0 + tig * 2];
                af[i][2] = *(const uint32_t*)&As2[buf][r    ][k0 + tig * 2 + 8];
                af[i][3] = *(const uint32_t*)&As2[buf][r + 8][k0 + tig * 2 + 8];
            }
#pragma unroll
            for (int j = 0; j < 5; j++) {
                int col = j * 8 + g;
                uint32_t bf[2];
                bf[0] = *(const uint32_t*)&ws2[col][st * 32 + k0 + tig * 2];
                bf[1] = *(const uint32_t*)&ws2[col][st * 32 + k0 + tig * 2 + 8];
                mma_f16(acc[0][j], af[0], bf, acc[0][j]);
                mma_f16(acc[1][j], af[1], bf, acc[1][j]);
            }
        }
    }
#undef LD_STAGE2

#pragma unroll
    for (int i = 0; i < 2; i++) {
        int r0 = row0 + rm + i*16 + g;
        int r1 = r0 + 8;
        float d0 = (r0 < NN) ? g_dinv[r0] : 0.f;
        float d1 = (r1 < NN) ? g_dinv[r1] : 0.f;
#pragma unroll
        for (int j = 0; j < 5; j++) {
            int cp = j*4 + tig;
            if (r0 < NN)
                g_t2h[(size_t)r0 * 20 + cp] = pack_h2(acc[i][j][0]*d0, acc[i][j][1]*d0);
            if (r1 < NN)
                g_t2h[(size_t)r1 * 20 + cp] = pack_h2(acc[i][j][2]*d1, acc[i][j][3]*d1);
        }
    }
}

// ---------------- AGG2 + bias + log_softmax: warp/node, 8-unroll ----------------
__global__ void __launch_bounds__(256) k_agg2(const float* __restrict__ b2,
                                              float* __restrict__ out) {
    int warp = (blockIdx.x * blockDim.x + threadIdx.x) >> 5;
    if (warp >= NN) return;
    int lane = threadIdx.x & 31;
    int node = warp;
    bool act = lane < 20;
    float dn = g_dinv[node];
    int cl = act ? lane : 0;
    float accx = 0.f, accy = 0.f;
    {
        float2 p = unpack_h2(g_t2h[(size_t)node * 20 + cl]);
        if (act) { accx = p.x; accy = p.y; }
    }
    const int2* __restrict__ E = g_csre;
    int e0 = g_rowstart[node], e1 = g_rowstart[node + 1];
    int e = e0;
#define EDGE2(q)                                                       \
    {                                                                  \
        float2 v = unpack_h2(g_t2h[(size_t)(q).x * 20 + cl]);          \
        if (act) { accx += v.x; accy += v.y; }                         \
    }
    for (; e + 8 <= e1; e += 8) {
        int2 q0 = E[e],   q1 = E[e+1], q2 = E[e+2], q3 = E[e+3];
        int2 q4 = E[e+4], q5 = E[e+5], q6 = E[e+6], q7 = E[e+7];
        EDGE2(q0) EDGE2(q1) EDGE2(q2) EDGE2(q3)
        EDGE2(q4) EDGE2(q5) EDGE2(q6) EDGE2(q7)
    }
    for (; e < e1; e++) { int2 q = E[e]; EDGE2(q) }
#undef EDGE2
    float lx = -1e30f, ly = -1e30f;
    if (act) {
        float2 bb = *(const float2*)&b2[lane * 2];
        lx = accx * dn + bb.x;
        ly = accy * dn + bb.y;
    }
    float m = fmaxf(lx, ly);
    for (int off = 16; off > 0; off >>= 1)
        m = fmaxf(m, __shfl_xor_sync(0xFFFFFFFF, m, off));
    float s = act ? (expf(lx - m) + expf(ly - m)) : 0.f;
    for (int off = 16; off > 0; off >>= 1)
        s += __shfl_xor_sync(0xFFFFFFFF, s, off);
    float lse = logf(s) + m;
    if (act) {
        float2 o = make_float2(lx - lse, ly - lse);
        *(float2*)&out[(size_t)node * NCLS + lane * 2] = o;
    }
}

// ---------------- launcher (gemm1 is the 4th launch -> gets profiled) ----------------
extern "C" void kernel_launch(void* const* d_in, const int* in_sizes, int n_in,
                              void* d_out, int out_size) {
    const float* x  = (const float*)d_in[0];
    const void*  ei = d_in[1];
    const float* W1 = (const float*)d_in[2];
    const float* b1 = (const float*)d_in[3];
    const float* W2 = (const float*)d_in[4];
    const float* b2 = (const float*)d_in[5];
    float* out = (float*)d_out;

    k_init<<<(NN + 255) / 256, 256>>>((const int*)ei, W1, W2);
    k_deg<<<(NE + 255) / 256, 256>>>(ei);
    k_scan1<<<98, 1024>>>();
    k_gemm1<<<(NN + 127) / 128, 256>>>(x);   // 4th launch: profiled
    k_scan3<<<98, 1024>>>();
    k_csr<<<(NE + 255) / 256, 256>>>(ei);
    k_agg1<<<(NN * 32 + 255) / 256, 256>>>(b1);
    k_gemm2<<<(NN + 127) / 128, 128>>>();
    k_agg2<<<(NN * 32 + 255) / 256, 256>>>(b2, out);
}

// round 17
// speedup vs baseline: 1.1098x; 1.0174x over previous
#include <cuda_runtime.h>
#include <cuda_fp16.h>
#include <math.h>
#include <stdint.h>

#define NN 100000
#define NE 1600000
#define INCH 512
#define HID 128
#define NCLS 40

// ---------------- device scratch ----------------
__device__ unsigned g_t1h[(size_t)NN * 64];   // x@W1 (UNSCALED) as fp16x2
__device__ unsigned g_hh [(size_t)NN * 64];   // relu(agg1) as fp16x2
__device__ unsigned g_t2h[(size_t)NN * 20];   // (h@W2)*dinv as fp16x2
__device__ __half   g_w1h[INCH * HID];        // W1 transposed [n][k] fp16
__device__ __half   g_w2h[HID * NCLS];        // W2 transposed [n][k] fp16
__device__ float    g_dinv[NN];
__device__ int      g_indeg[NN];
__device__ int      g_rowstart[NN + 1];
__device__ int      g_cursor[NN];
__device__ int2     g_csre[NE];               // (src, dinv[src] bits)
__device__ int      g_part[256];
__device__ int      g_is64;

// ---------------- helpers ----------------
__device__ __forceinline__ void mma_f16(float* d, const uint32_t* a,
                                        const uint32_t* b, const float* c) {
    asm volatile(
        "mma.sync.aligned.m16n8k16.row.col.f32.f16.f16.f32 "
        "{%0,%1,%2,%3}, {%4,%5,%6,%7}, {%8,%9}, {%10,%11,%12,%13};\n"
        : "=f"(d[0]), "=f"(d[1]), "=f"(d[2]), "=f"(d[3])
        : "r"(a[0]), "r"(a[1]), "r"(a[2]), "r"(a[3]),
          "r"(b[0]), "r"(b[1]),
          "f"(c[0]), "f"(c[1]), "f"(c[2]), "f"(c[3]));
}

__device__ __forceinline__ void cpa16(void* smem, const void* gmem, int sz) {
    unsigned s = (unsigned)__cvta_generic_to_shared(smem);
    asm volatile("cp.async.cg.shared.global [%0], [%1], 16, %2;\n"
                 :: "r"(s), "l"(gmem), "r"(sz));
}

__device__ __forceinline__ unsigned pack_h2(float a, float b) {
    __half2 v = __floats2half2_rn(a, b);
    return *(unsigned*)&v;
}

__device__ __forceinline__ float2 unpack_h2(unsigned u) {
    return __half22float2(*(__half2*)&u);
}

// ---------------- init: zero + dtype detect + weight convert ----------------
__global__ void k_init(const int* ei, const float* __restrict__ W1,
                       const float* __restrict__ W2) {
    int i = blockIdx.x * blockDim.x + threadIdx.x;
    if (i < NN) { g_indeg[i] = 0; g_cursor[i] = 0; }
    if (i < INCH * HID) {               // W1[k][n] -> g_w1h[n][k]
        int k = i >> 7, n = i & 127;
        g_w1h[n * INCH + k] = __float2half(W1[i]);
    }
    if (i < HID * NCLS) {               // W2[k][n] -> g_w2h[n][k]
        int k = i / NCLS, n = i % NCLS;
        g_w2h[n * HID + k] = __float2half(W2[i]);
    }
    if (i == 0) {
        int is64 = 1;
        for (int j = 0; j < 64; j++)
            if (ei[2 * j + 1] != 0) { is64 = 0; break; }
        g_is64 = is64;
    }
}

// ---------------- degree: 2 edges/thread, 16B loads ----------------
__global__ void k_deg(const void* ei) {
    int p = blockIdx.x * blockDim.x + threadIdx.x;   // pair index
    int e = p * 2;
    if (e < NE) {
        if (g_is64) {
            longlong2 d = ((const longlong2*)ei)[(NE + e) >> 1];
            atomicAdd(&g_indeg[(int)d.x], 1);
            atomicAdd(&g_indeg[(int)d.y], 1);
        } else {
            int2 d = ((const int2*)ei)[(NE + e) >> 1];
            atomicAdd(&g_indeg[d.x], 1);
            atomicAdd(&g_indeg[d.y], 1);
        }
    }
}

// ---------------- scan (warp-shuffle) ----------------
__global__ void k_scan1() {
    __shared__ int wsum[32];
    int tid = threadIdx.x, lane = tid & 31, wid = tid >> 5;
    int i = blockIdx.x * 1024 + tid;
    int v = (i < NN) ? g_indeg[i] : 0;
    for (int o = 16; o > 0; o >>= 1) v += __shfl_xor_sync(~0u, v, o);
    if (lane == 0) wsum[wid] = v;
    __syncthreads();
    if (wid == 0) {
        int a = wsum[lane];
        for (int o = 16; o > 0; o >>= 1) a += __shfl_xor_sync(~0u, a, o);
        if (lane == 0) g_part[blockIdx.x] = a;
    }
}

__global__ void k_scan3() {
    __shared__ int woff[32];
    __shared__ int sbase;
    int tid = threadIdx.x, lane = tid & 31, wid = tid >> 5;
    int bid = blockIdx.x;
    int i = bid * 1024 + tid;
    int v = (i < NN) ? g_indeg[i] : 0;
    // warp inclusive scan
    int x = v;
    for (int o = 1; o < 32; o <<= 1) {
        int y = __shfl_up_sync(~0u, x, o);
        if (lane >= o) x += y;
    }
    if (lane == 31) woff[wid] = x;   // warp totals
    // warp 1 computes base = sum of preceding block partials
    if (wid == 1) {
        int a = 0;
        for (int j = lane; j < bid; j += 32) a += g_part[j];
        for (int o = 16; o > 0; o >>= 1) a += __shfl_xor_sync(~0u, a, o);
        if (lane == 0) sbase = a;
    }
    __syncthreads();
    if (wid == 0) {
        int wv = woff[lane];
        int y = wv;
        for (int o = 1; o < 32; o <<= 1) {
            int z = __shfl_up_sync(~0u, y, o);
            if (lane >= o) y += z;
        }
        woff[lane] = y - wv;         // exclusive warp offsets
    }
    __syncthreads();
    if (i < NN) {
        int base = sbase + woff[wid];
        g_rowstart[i] = base + x - v;            // exclusive
        g_dinv[i] = rsqrtf((float)(v + 1));
        if (i == NN - 1) g_rowstart[NN] = base + x;
    }
}

// ---------------- CSR fill: 2 edges/thread, (src, dinv[src]) per edge ----------------
__global__ void k_csr(const void* ei) {
    int p = blockIdx.x * blockDim.x + threadIdx.x;
    int e = p * 2;
    if (e < NE) {
        int s0, s1, d0, d1;
        if (g_is64) {
            longlong2 sv = ((const longlong2*)ei)[e >> 1];
            longlong2 dv = ((const longlong2*)ei)[(NE + e) >> 1];
            s0 = (int)sv.x; s1 = (int)sv.y; d0 = (int)dv.x; d1 = (int)dv.y;
        } else {
            int2 sv = ((const int2*)ei)[e >> 1];
            int2 dv = ((const int2*)ei)[(NE + e) >> 1];
            s0 = sv.x; s1 = sv.y; d0 = dv.x; d1 = dv.y;
        }
        int pos0 = g_rowstart[d0] + atomicAdd(&g_cursor[d0], 1);
        g_csre[pos0] = make_int2(s0, __float_as_int(g_dinv[s0]));
        int pos1 = g_rowstart[d1] + atomicAdd(&g_cursor[d1], 1);
        g_csre[pos1] = make_int2(s1, __float_as_int(g_dinv[s1]));
    }
}

// ---------------- GEMM1 (fp16 mma, 4-stage cp.async — round-10 winner) ----------------
// block 128M x 128N, 8 warps (4x2), warp tile 32x64, K stage 16, 4-deep pipeline
#define G1_STAGES 4
#define G1_ABYTES (G1_STAGES * 128 * 24 * 4)
#define G1_SMEM   (G1_ABYTES + G1_STAGES * 128 * 24 * 2)

__global__ void __launch_bounds__(256) k_gemm1(const float* __restrict__ A) {
    extern __shared__ __align__(16) char dsm[];
    float*  As = (float*)dsm;                      // [4][128][24]
    __half* Bs = (__half*)(dsm + G1_ABYTES);       // [4][128][24]
#define AS(b, r, c) As[(((b) * 128) + (r)) * 24 + (c)]
#define BS(b, r, c) Bs[(((b) * 128) + (r)) * 24 + (c)]

    int t = threadIdx.x, lane = t & 31, w = t >> 5;
    int wm = w >> 1, wn = w & 1;
    int row0 = blockIdx.x * 128;
    int g = lane >> 2, tig = lane & 3;
    int rm = wm * 32, cn = wn * 64;

    int arow = t >> 1;
    int acol = (t & 1) * 8;
    int bn   = t >> 1;
    int bc   = (t & 1) * 8;

    float acc[2][8][4];
#pragma unroll
    for (int i = 0; i < 2; i++)
#pragma unroll
        for (int j = 0; j < 8; j++)
#pragma unroll
            for (int q = 0; q < 4; q++) acc[i][j][q] = 0.f;

    int aok = (row0 + arow < NN) ? 16 : 0;
    const float* abase = &A[(size_t)(row0 + arow) * INCH];

#define LOAD_STAGE(buf, k0)                                               \
    {                                                                     \
        const float* ap = abase + (k0) + acol;                            \
        cpa16(&AS(buf, arow, acol), ap, aok);                             \
        cpa16(&AS(buf, arow, acol + 4), ap + 4, aok);                     \
        cpa16(&BS(buf, bn, bc), &g_w1h[bn * INCH + (k0) + bc], 16);       \
    }

    LOAD_STAGE(0, 0);
    asm volatile("cp.async.commit_group;\n");
    LOAD_STAGE(1, 16);
    asm volatile("cp.async.commit_group;\n");
    LOAD_STAGE(2, 32);
    asm volatile("cp.async.commit_group;\n");

    for (int s = 0; s < 32; s++) {
        int buf = s & 3;
        asm volatile("cp.async.wait_group 2;\n");
        __syncthreads();

        uint32_t af[2][4];
#pragma unroll
        for (int i = 0; i < 2; i++) {
            int r = rm + i * 16 + g;
            float2 v0 = *(const float2*)&AS(buf, r,     tig * 2);
            float2 v1 = *(const float2*)&AS(buf, r + 8, tig * 2);
            float2 v2 = *(const float2*)&AS(buf, r,     tig * 2 + 8);
            float2 v3 = *(const float2*)&AS(buf, r + 8, tig * 2 + 8);
            af[i][0] = pack_h2(v0.x, v0.y);
            af[i][1] = pack_h2(v1.x, v1.y);
            af[i][2] = pack_h2(v2.x, v2.y);
            af[i][3] = pack_h2(v3.x, v3.y);
        }
#pragma unroll
        for (int j = 0; j < 8; j++) {
            int col = cn + j * 8 + g;
            uint32_t bf[2];
            bf[0] = *(const uint32_t*)&BS(buf, col, tig * 2);
            bf[1] = *(const uint32_t*)&BS(buf, col, tig * 2 + 8);
            mma_f16(acc[0][j], af[0], bf, acc[0][j]);
            mma_f16(acc[1][j], af[1], bf, acc[1][j]);
        }
        if (s < 29) LOAD_STAGE((s + 3) & 3, (s + 3) * 16);
        asm volatile("cp.async.commit_group;\n");
    }
#undef LOAD_STAGE
#undef AS
#undef BS

#pragma unroll
    for (int i = 0; i < 2; i++) {
        int r0 = row0 + rm + i*16 + g;
        int r1 = r0 + 8;
#pragma unroll
        for (int j = 0; j < 8; j++) {
            int cp = (cn >> 1) + j*4 + tig;
            if (r0 < NN)
                g_t1h[(size_t)r0 * 64 + cp] = pack_h2(acc[i][j][0], acc[i][j][1]);
            if (r1 < NN)
                g_t1h[(size_t)r1 * 64 + cp] = pack_h2(acc[i][j][2], acc[i][j][3]);
        }
    }
}

// ---------------- AGG1: warp/node, 8-unroll, per-edge dinv from csre ----------------
__global__ void __launch_bounds__(256) k_agg1(const float* __restrict__ b1) {
    int warp = (blockIdx.x * blockDim.x + threadIdx.x) >> 5;
    if (warp >= NN) return;
    int lane = threadIdx.x & 31;
    int node = warp;
    float dn = g_dinv[node];
    const uint2* __restrict__ T = (const uint2*)g_t1h;
    const int2* __restrict__ E = g_csre;
    uint2 sv = T[(size_t)node * 32 + lane];
    float2 p0 = unpack_h2(sv.x), p1 = unpack_h2(sv.y);
    float ax = p0.x * dn, ay = p0.y * dn, az = p1.x * dn, aw = p1.y * dn;
    int e0 = g_rowstart[node], e1 = g_rowstart[node + 1];
    int e = e0;
#define EDGE(q, v)                                                     \
    {                                                                  \
        float dd = __int_as_float((q).y);                              \
        float2 a = unpack_h2((v).x), c = unpack_h2((v).y);             \
        ax += a.x * dd; ay += a.y * dd;                                \
        az += c.x * dd; aw += c.y * dd;                                \
    }
    for (; e + 8 <= e1; e += 8) {
        int2 q0 = E[e],   q1 = E[e+1], q2 = E[e+2], q3 = E[e+3];
        int2 q4 = E[e+4], q5 = E[e+5], q6 = E[e+6], q7 = E[e+7];
        uint2 v0 = T[(size_t)q0.x * 32 + lane];
        uint2 v1 = T[(size_t)q1.x * 32 + lane];
        uint2 v2 = T[(size_t)q2.x * 32 + lane];
        uint2 v3 = T[(size_t)q3.x * 32 + lane];
        uint2 v4 = T[(size_t)q4.x * 32 + lane];
        uint2 v5 = T[(size_t)q5.x * 32 + lane];
        uint2 v6 = T[(size_t)q6.x * 32 + lane];
        uint2 v7 = T[(size_t)q7.x * 32 + lane];
        EDGE(q0, v0) EDGE(q1, v1) EDGE(q2, v2) EDGE(q3, v3)
        EDGE(q4, v4) EDGE(q5, v5) EDGE(q6, v6) EDGE(q7, v7)
    }
    for (; e < e1; e++) {
        int2 q = E[e];
        uint2 v = T[(size_t)q.x * 32 + lane];
        EDGE(q, v)
    }
#undef EDGE
    float4 bb = *(const float4*)&b1[lane * 4];
    float hx = fmaxf(ax * dn + bb.x, 0.f);
    float hy = fmaxf(ay * dn + bb.y, 0.f);
    float hz = fmaxf(az * dn + bb.z, 0.f);
    float hw = fmaxf(aw * dn + bb.w, 0.f);
    uint2 o = make_uint2(pack_h2(hx, hy), pack_h2(hz, hw));
    ((uint2*)g_hh)[(size_t)node * 32 + lane] = o;
}

// ---------------- GEMM2 (fp16 mma, 3-buffer pipeline): t2h = fp16((h@W2)*dinv) ----------
__global__ void __launch_bounds__(128) k_gemm2() {
    __shared__ __align__(16) __half As2[3][128][40];
    __shared__ __align__(16) __half ws2[40][136];
    int t = threadIdx.x, lane = t & 31, w = t >> 5;
    int row0 = blockIdx.x * 128;
    int g = lane >> 2, tig = lane & 3;
    int rm = w * 32;

    for (int i = t; i < NCLS * HID; i += 128)
        ws2[i >> 7][i & 127] = g_w2h[i];

    float acc[2][5][4];
#pragma unroll
    for (int i = 0; i < 2; i++)
#pragma unroll
        for (int j = 0; j < 5; j++)
#pragma unroll
            for (int q = 0; q < 4; q++) acc[i][j][q] = 0.f;

    const __half* hbase = (const __half*)g_hh;

#define LD_STAGE2(buf, st)                                             \
    {                                                                  \
        _Pragma("unroll")                                              \
        for (int i = 0; i < 4; i++) {                                  \
            int f = t + i * 128;                                       \
            int r = f >> 2, c = (f & 3) * 8;                           \
            int ok = (row0 + r < NN) ? 16 : 0;                         \
            cpa16(&As2[buf][r][c],                                     \
                  hbase + (size_t)(row0 + r) * HID + (st) * 32 + c, ok); \
        }                                                              \
        asm volatile("cp.async.commit_group;\n");                      \
    }

    LD_STAGE2(0, 0);
    LD_STAGE2(1, 1);

    for (int st = 0; st < 4; st++) {
        int buf = st % 3;
        asm volatile("cp.async.wait_group 1;\n");
        __syncthreads();
        if (st + 2 < 4) { LD_STAGE2((st + 2) % 3, st + 2); }
        else { asm volatile("cp.async.commit_group;\n"); }

#pragma unroll
        for (int kh = 0; kh < 2; kh++) {
            int k0 = kh * 16;
            uint32_t af[2][4];
#pragma unroll
            for (int i = 0; i < 2; i++) {
                int r = rm + i * 16 + g;
                af[i][0] = *(const uint32_t*)&As2[buf][r    ][k0 + tig * 2];
                af[i][1] = *(const uint32_t*)&As2[buf][r + 8][k0 + tig * 2];
                af[i][2] = *(const uint32_t*)&As2[buf][r    ][k0 + tig * 2 + 8];
                af[i][3] = *(const uint32_t*)&As2[buf][r + 8][k0 + tig * 2 + 8];
            }
#pragma unroll
            for (int j = 0; j < 5; j++) {
                int col = j * 8 + g;
                uint32_t bf[2];
                bf[0] = *(const uint32_t*)&ws2[col][st * 32 + k0 + tig * 2];
                bf[1] = *(const uint32_t*)&ws2[col][st * 32 + k0 + tig * 2 + 8];
                mma_f16(acc[0][j], af[0], bf, acc[0][j]);
                mma_f16(acc[1][j], af[1], bf, acc[1][j]);
            }
        }
    }
#undef LD_STAGE2

#pragma unroll
    for (int i = 0; i < 2; i++) {
        int r0 = row0 + rm + i*16 + g;
        int r1 = r0 + 8;
        float d0 = (r0 < NN) ? g_dinv[r0] : 0.f;
        float d1 = (r1 < NN) ? g_dinv[r1] : 0.f;
#pragma unroll
        for (int j = 0; j < 5; j++) {
            int cp = j*4 + tig;
            if (r0 < NN)
                g_t2h[(size_t)r0 * 20 + cp] = pack_h2(acc[i][j][0]*d0, acc[i][j][1]*d0);
            if (r1 < NN)
                g_t2h[(size_t)r1 * 20 + cp] = pack_h2(acc[i][j][2]*d1, acc[i][j][3]*d1);
        }
    }
}

// ---------------- AGG2 + bias + log_softmax: warp/node, 8-unroll ----------------
__global__ void __launch_bounds__(256) k_agg2(const float* __restrict__ b2,
                                              float* __restrict__ out) {
    int warp = (blockIdx.x * blockDim.x + threadIdx.x) >> 5;
    if (warp >= NN) return;
    int lane = threadIdx.x & 31;
    int node = warp;
    bool act = lane < 20;
    float dn = g_dinv[node];
    int cl = act ? lane : 0;
    float accx = 0.f, accy = 0.f;
    {
        float2 p = unpack_h2(g_t2h[(size_t)node * 20 + cl]);
        if (act) { accx = p.x; accy = p.y; }
    }
    const int2* __restrict__ E = g_csre;
    int e0 = g_rowstart[node], e1 = g_rowstart[node + 1];
    int e = e0;
#define EDGE2(q)                                                       \
    {                                                                  \
        float2 v = unpack_h2(g_t2h[(size_t)(q).x * 20 + cl]);          \
        if (act) { accx += v.x; accy += v.y; }                         \
    }
    for (; e + 8 <= e1; e += 8) {
        int2 q0 = E[e],   q1 = E[e+1], q2 = E[e+2], q3 = E[e+3];
        int2 q4 = E[e+4], q5 = E[e+5], q6 = E[e+6], q7 = E[e+7];
        EDGE2(q0) EDGE2(q1) EDGE2(q2) EDGE2(q3)
        EDGE2(q4) EDGE2(q5) EDGE2(q6) EDGE2(q7)
    }
    for (; e < e1; e++) { int2 q = E[e]; EDGE2(q) }
#undef EDGE2
    float lx = -1e30f, ly = -1e30f;
    if (act) {
        float2 bb = *(const float2*)&b2[lane * 2];
        lx = accx * dn + bb.x;
        ly = accy * dn + bb.y;
    }
    float m = fmaxf(lx, ly);
    for (int off = 16; off > 0; off >>= 1)
        m = fmaxf(m, __shfl_xor_sync(0xFFFFFFFF, m, off));
    float s = act ? (expf(lx - m) + expf(ly - m)) : 0.f;
    for (int off = 16; off > 0; off >>= 1)
        s += __shfl_xor_sync(0xFFFFFFFF, s, off);
    float lse = logf(s) + m;
    if (act) {
        float2 o = make_float2(lx - lse, ly - lse);
        *(float2*)&out[(size_t)node * NCLS + lane * 2] = o;
    }
}

// ---------------- launcher (gemm1 is the 4th launch -> gets profiled) ----------------
extern "C" void kernel_launch(void* const* d_in, const int* in_sizes, int n_in,
                              void* d_out, int out_size) {
    const float* x  = (const float*)d_in[0];
    const void*  ei = d_in[1];
    const float* W1 = (const float*)d_in[2];
    const float* b1 = (const float*)d_in[3];
    const float* W2 = (const float*)d_in[4];
    const float* b2 = (const float*)d_in[5];
    float* out = (float*)d_out;

    cudaFuncSetAttribute(k_gemm1, cudaFuncAttributeMaxDynamicSharedMemorySize,
                         G1_SMEM);

    k_init<<<(NN + 255) / 256, 256>>>((const int*)ei, W1, W2);
    k_deg<<<(NE / 2 + 255) / 256, 256>>>(ei);
    k_scan1<<<98, 1024>>>();
    k_gemm1<<<(NN + 127) / 128, 256, G1_SMEM>>>(x);   // 4th launch: profiled
    k_scan3<<<98, 1024>>>();
    k_csr<<<(NE / 2 + 255) / 256, 256>>>(ei);
    k_agg1<<<(NN * 32 + 255) / 256, 256>>>(b1);
    k_gemm2<<<(NN + 127) / 128, 128>>>();
    k_agg2<<<(NN * 32 + 255) / 256, 256>>>(b2, out);
}